// round 12
// baseline (speedup 1.0000x reference)
#include <cuda_runtime.h>
#include <cuda_bf16.h>

#define NBINS 256
#define NCH 3
#define NHIST (NBINS * NCH)       // 768
#define BLOCK_THREADS 512
#define GRID_BLOCKS 294           // divisible by 3; 2 CTAs/SM, one full wave
// stride = 294*512 = 150528, % 3 == 0 -> channel phase is loop-invariant.

#define SMEM_WORDS (NHIST * 32)   // 24576 words = 96 KB (dynamic)
#define SMEM_BYTES (SMEM_WORDS * 4)

// Zero at module load; the fused last-block finalize re-zeroes after reading,
// so every call (correctness run and each graph replay) starts from zero.
__device__ unsigned int g_counts[NHIST];
__device__ unsigned int g_ticket;

// Exact bin*128 byte-offset for x in [0,1), with zero cvt-pipe usage:
//   y = rz(x + 1.0f) in [1,2): mantissa = trunc(x * 2^23), so
//   floor(x*256) = mantissa >> 15, and bin*128 = (bits(y) >> 8) & 0x7F80.
// Truncation (rz) can never cross a 2^-8 bin boundary -> exact vs int(x*256).
// The mask bounds the offset to [0, 255*128] for ANY input (memory-safe).
__device__ __forceinline__ unsigned int bin_off(float x) {
    float y;
    asm("add.rz.f32 %0, %1, 0f3F800000;" : "=f"(y) : "f"(x));
    return (__float_as_uint(y) >> 8) & 0x7F80u;
}

__global__ void __launch_bounds__(BLOCK_THREADS, 2)
hist_kernel(const float4* __restrict__ in4, int n4,
            const float* __restrict__ in, int n_total,
            float* __restrict__ out, float inv_total) {
    // Fully lane-private layout: counter (c, bin, lane) at
    //   sh[(c*256 + bin)*32 + lane]  ->  bank = lane, conflict degree 1 always.
    extern __shared__ unsigned int sh[];   // 96 KB -> 2 CTAs/SM

    {   // zero with 128-bit stores
        uint4* s4 = (uint4*)sh;
        uint4 z = make_uint4(0u, 0u, 0u, 0u);
        for (int i = threadIdx.x; i < SMEM_WORDS / 4; i += BLOCK_THREADS)
            s4[i] = z;
    }
    __syncthreads();

    const int lane = threadIdx.x & 31;
    const int stride = GRID_BLOCKS * BLOCK_THREADS;   // % 3 == 0
    int j0 = blockIdx.x * BLOCK_THREADS + threadIdx.x;

    // Channel phase (loop-invariant): float4 j holds channels c0,c0+1,c0+2,c0.
    int c0 = j0 % 3;
    int c1 = c0 + 1; if (c1 == 3) c1 = 0;
    int c2 = c1 + 1; if (c2 == 3) c2 = 0;
    char* b0 = (char*)(sh + c0 * (NBINS * 32) + lane);
    char* b1 = (char*)(sh + c1 * (NBINS * 32) + lane);
    char* b2 = (char*)(sh + c2 * (NBINS * 32) + lane);

    #define ACC(base, xv) \
        atomicAdd((unsigned int*)((base) + bin_off(xv)), 1u)

    // Main loop: 4 front-batched loads (MLP_p1 = 4), then 16 shared atomics.
    int j = j0;
    for (; j + 3 * stride < n4; j += 4 * stride) {
        float4 a = in4[j];
        float4 b = in4[j + stride];
        float4 c = in4[j + 2 * stride];
        float4 d = in4[j + 3 * stride];

        ACC(b0, a.x); ACC(b1, a.y); ACC(b2, a.z); ACC(b0, a.w);
        ACC(b0, b.x); ACC(b1, b.y); ACC(b2, b.z); ACC(b0, b.w);
        ACC(b0, c.x); ACC(b1, c.y); ACC(b2, c.z); ACC(b0, c.w);
        ACC(b0, d.x); ACC(b1, d.y); ACC(b2, d.z); ACC(b0, d.w);
    }
    for (; j < n4; j += stride) {
        float4 a = in4[j];
        ACC(b0, a.x); ACC(b1, a.y); ACC(b2, a.z); ACC(b0, a.w);
    }

    // Scalar tail (n_total % 4 != 0) — block 0 only (no-op for this shape)
    if (blockIdx.x == 0) {
        for (int i = n4 * 4 + threadIdx.x; i < n_total; i += BLOCK_THREADS) {
            int c = i % 3;
            char* bc = (char*)(sh + c * (NBINS * 32) + lane);
            ACC(bc, in[i]);
        }
    }

    __syncthreads();

    // Warp-cooperative reduction: one LDS + REDUX per bin per warp.
    // Lane l reads column l of bin i (banks 0..31, conflict-free).
    const int wid = threadIdx.x >> 5;                 // 16 warps
    for (int i = wid; i < NHIST; i += BLOCK_THREADS / 32) {
        unsigned int v = sh[i * 32 + lane];
        unsigned int s = __reduce_add_sync(0xFFFFFFFFu, v);
        if (lane == 0 && s) atomicAdd(&g_counts[i], s);
    }

    // Fused finalize: last block to arrive normalizes and resets state.
    __threadfence();
    __shared__ unsigned int ticket;
    if (threadIdx.x == 0) ticket = atomicAdd(&g_ticket, 1u);
    __syncthreads();
    if (ticket == GRID_BLOCKS - 1) {
        for (int i = threadIdx.x; i < NHIST; i += BLOCK_THREADS) {
            unsigned int s = atomicAdd(&g_counts[i], 0u);   // coherent read
            g_counts[i] = 0u;                               // reset for next call
            int c   = i >> 8;
            int bin = i & (NBINS - 1);
            // reference output is hist.T -> [nbins, 3] row-major
            out[bin * NCH + c] = (float)s * inv_total;
        }
        if (threadIdx.x == 0) g_ticket = 0u;                // reset ticket
    }
}

extern "C" void kernel_launch(void* const* d_in, const int* in_sizes, int n_in,
                              void* d_out, int out_size) {
    const float* in = (const float*)d_in[0];
    int n = in_sizes[0];                 // 64*512*512*3 = 50,331,648
    int n4 = n / 4;
    float inv_total = 1.0f / (float)(n / 3);   // per-channel pixel count (exact)

    // Raise dynamic-smem limit for the 96 KB table (idempotent, capture-safe).
    cudaFuncSetAttribute(hist_kernel,
                         cudaFuncAttributeMaxDynamicSharedMemorySize, SMEM_BYTES);

    hist_kernel<<<GRID_BLOCKS, BLOCK_THREADS, SMEM_BYTES>>>(
        (const float4*)in, n4, in, n, (float*)d_out, inv_total);
}

// round 13
// speedup vs baseline: 1.0729x; 1.0729x over previous
#include <cuda_runtime.h>
#include <cuda_bf16.h>

#define NBINS 256
#define NCH 3
#define NHIST (NBINS * NCH)       // 768
#define BLOCK_THREADS 512
#define GRID_BLOCKS 294           // divisible by 3; 2 CTAs/SM, one full wave
// stride = 294*512 = 150528, % 3 == 0 -> channel phase is loop-invariant.

#define SMEM_WORDS (NHIST * 32)   // 24576 words = 96 KB (dynamic)
#define SMEM_BYTES (SMEM_WORDS * 4)

// Zero at module load; the fused last-block finalize re-zeroes after reading,
// so every call (correctness run and each graph replay) starts from zero.
__device__ unsigned int g_counts[NHIST];
__device__ unsigned int g_ticket;

// Exact word-index bin*32 for x in [0,1), no cvt pipe, no clamps:
//   y = rz(x + 1.0f) in [1,2): mantissa = trunc(x * 2^23), so
//   floor(x*256) = bits(y)>>15 - 0x7F00... i.e. bin = (bits(y)>>15) & 0xFF,
//   and bin*32 = (bits(y) >> 10) & 0x1FE0.
// rz truncation cannot cross a 2^-8 bin boundary -> exact vs int(x*256).
// The mask bounds the index for ANY input (memory-safe).
__device__ __forceinline__ unsigned int bin_w32(float x) {
    float y = __fadd_rz(x, 1.0f);
    return (__float_as_uint(y) >> 10) & 0x1FE0u;   // bin * 32
}

__global__ void __launch_bounds__(BLOCK_THREADS, 2)
hist_kernel(const float4* __restrict__ in4, int n4,
            const float* __restrict__ in, int n_total,
            float* __restrict__ out, float inv_total) {
    // Fully lane-private layout: counter (c, bin, lane) at
    //   sh[(c*256 + bin)*32 + lane]  ->  bank = lane, conflict degree 1 always.
    extern __shared__ unsigned int sh[];   // 96 KB -> 2 CTAs/SM

    {   // zero with 128-bit stores
        uint4* s4 = (uint4*)sh;
        uint4 z = make_uint4(0u, 0u, 0u, 0u);
        for (int i = threadIdx.x; i < SMEM_WORDS / 4; i += BLOCK_THREADS)
            s4[i] = z;
    }
    __syncthreads();

    const int lane = threadIdx.x & 31;
    const int stride = GRID_BLOCKS * BLOCK_THREADS;   // % 3 == 0
    int j0 = blockIdx.x * BLOCK_THREADS + threadIdx.x;

    // Channel phase (loop-invariant): float4 j holds channels c0,c0+1,c0+2,c0.
    int c0 = j0 % 3;
    int c1 = c0 + 1; if (c1 == 3) c1 = 0;
    int c2 = c1 + 1; if (c2 == 3) c2 = 0;
    unsigned int* p0 = sh + c0 * (NBINS * 32) + lane;
    unsigned int* p1 = sh + c1 * (NBINS * 32) + lane;
    unsigned int* p2 = sh + c2 * (NBINS * 32) + lane;

    #define ACC(p, xv) atomicAdd(&(p)[bin_w32(xv)], 1u)

    // Main loop: 4 front-batched loads (MLP_p1 = 4), then 16 shared atomics.
    int j = j0;
    for (; j + 3 * stride < n4; j += 4 * stride) {
        float4 a = in4[j];
        float4 b = in4[j + stride];
        float4 c = in4[j + 2 * stride];
        float4 d = in4[j + 3 * stride];

        ACC(p0, a.x); ACC(p1, a.y); ACC(p2, a.z); ACC(p0, a.w);
        ACC(p0, b.x); ACC(p1, b.y); ACC(p2, b.z); ACC(p0, b.w);
        ACC(p0, c.x); ACC(p1, c.y); ACC(p2, c.z); ACC(p0, c.w);
        ACC(p0, d.x); ACC(p1, d.y); ACC(p2, d.z); ACC(p0, d.w);
    }
    for (; j < n4; j += stride) {
        float4 a = in4[j];
        ACC(p0, a.x); ACC(p1, a.y); ACC(p2, a.z); ACC(p0, a.w);
    }

    // Scalar tail (n_total % 4 != 0) — block 0 only (no-op for this shape)
    if (blockIdx.x == 0) {
        for (int i = n4 * 4 + threadIdx.x; i < n_total; i += BLOCK_THREADS) {
            int c = i % 3;
            atomicAdd(&sh[c * (NBINS * 32) + lane + bin_w32(in[i])], 1u);
        }
    }

    __syncthreads();

    // Warp-cooperative reduction: one LDS + REDUX per bin per warp.
    // Lane l reads column l of bin i (banks 0..31, conflict-free).
    const int wid = threadIdx.x >> 5;                 // 16 warps
    for (int i = wid; i < NHIST; i += BLOCK_THREADS / 32) {
        unsigned int v = sh[i * 32 + lane];
        unsigned int s = __reduce_add_sync(0xFFFFFFFFu, v);
        if (lane == 0 && s) atomicAdd(&g_counts[i], s);
    }

    // Fused finalize: last block to arrive normalizes and resets state.
    __threadfence();
    __shared__ unsigned int ticket;
    if (threadIdx.x == 0) ticket = atomicAdd(&g_ticket, 1u);
    __syncthreads();
    if (ticket == GRID_BLOCKS - 1) {
        for (int i = threadIdx.x; i < NHIST; i += BLOCK_THREADS) {
            unsigned int s = atomicAdd(&g_counts[i], 0u);   // coherent read
            g_counts[i] = 0u;                               // reset for next call
            int c   = i >> 8;
            int bin = i & (NBINS - 1);
            // reference output is hist.T -> [nbins, 3] row-major
            out[bin * NCH + c] = (float)s * inv_total;
        }
        if (threadIdx.x == 0) g_ticket = 0u;                // reset ticket
    }
}

extern "C" void kernel_launch(void* const* d_in, const int* in_sizes, int n_in,
                              void* d_out, int out_size) {
    const float* in = (const float*)d_in[0];
    int n = in_sizes[0];                 // 64*512*512*3 = 50,331,648
    int n4 = n / 4;
    float inv_total = 1.0f / (float)(n / 3);   // per-channel pixel count (exact)

    // Raise dynamic-smem limit for the 96 KB table (idempotent, capture-safe).
    cudaFuncSetAttribute(hist_kernel,
                         cudaFuncAttributeMaxDynamicSharedMemorySize, SMEM_BYTES);

    hist_kernel<<<GRID_BLOCKS, BLOCK_THREADS, SMEM_BYTES>>>(
        (const float4*)in, n4, in, n, (float*)d_out, inv_total);
}

// round 14
// speedup vs baseline: 2.1342x; 1.9892x over previous
#include <cuda_runtime.h>
#include <cuda_bf16.h>

#define NBINS 256
#define NCH 3
#define NHIST (NBINS * NCH)       // 768
#define BLOCK_THREADS 512
#define GRID_BLOCKS 294           // divisible by 3; 2 CTAs/SM fits one wave (296)
// stride = 294*512 = 150528, % 3 == 0 -> channel phase is loop-invariant.

#define SMEM_WORDS (NHIST * 32)   // 24576 words = 96 KB (dynamic)
#define SMEM_BYTES (SMEM_WORDS * 4)

// Zero at module load; the fused last-block finalize re-zeroes after reading,
// so every call (correctness run and each graph replay) starts from zero.
__device__ unsigned int g_counts[NHIST];
__device__ unsigned int g_ticket;

__device__ __forceinline__ int bin_of(float x) {
    // TF histogram_fixed_width rule: clip(int(x*256), 0, 255), trunc toward zero
    int b = __float2int_rz(x * 256.0f);
    return max(0, min(255, b));
}

__global__ void __launch_bounds__(BLOCK_THREADS, 2)
hist_kernel(const float4* __restrict__ in4, int n4,
            const float* __restrict__ in, int n_total,
            float* __restrict__ out, float inv_total) {
    // Fully lane-private layout: counter (c, bin, lane) at
    //   sh[(c*256 + bin)*32 + lane]
    // Bank = lane for EVERY access -> smem atomic conflict degree 1, always,
    // and the address is one LEA (bin<<7 + channel base). No packing ALU.
    extern __shared__ unsigned int sh[];   // 96 KB -> 2 CTAs/SM

    {   // zero with 128-bit stores
        uint4* s4 = (uint4*)sh;
        uint4 z = make_uint4(0u, 0u, 0u, 0u);
        for (int i = threadIdx.x; i < SMEM_WORDS / 4; i += BLOCK_THREADS)
            s4[i] = z;
    }
    __syncthreads();

    const int lane = threadIdx.x & 31;
    const int stride = GRID_BLOCKS * BLOCK_THREADS;   // % 3 == 0
    int j0 = blockIdx.x * BLOCK_THREADS + threadIdx.x;

    // Channel phase (loop-invariant): float4 j holds channels c0,c0+1,c0+2,c0.
    int c0 = j0 % 3;
    int c1 = c0 + 1; if (c1 == 3) c1 = 0;
    int c2 = c1 + 1; if (c2 == 3) c2 = 0;
    unsigned int* p0 = sh + c0 * (NBINS * 32) + lane;
    unsigned int* p1 = sh + c1 * (NBINS * 32) + lane;
    unsigned int* p2 = sh + c2 * (NBINS * 32) + lane;

    #define ACC(p, xv) atomicAdd(&(p)[bin_of(xv) * 32], 1u)

    // Main loop: 4 front-batched loads (MLP_p1 = 4), then 16 shared atomics.
    int j = j0;
    for (; j + 3 * stride < n4; j += 4 * stride) {
        float4 a = in4[j];
        float4 b = in4[j + stride];
        float4 c = in4[j + 2 * stride];
        float4 d = in4[j + 3 * stride];

        ACC(p0, a.x); ACC(p1, a.y); ACC(p2, a.z); ACC(p0, a.w);
        ACC(p0, b.x); ACC(p1, b.y); ACC(p2, b.z); ACC(p0, b.w);
        ACC(p0, c.x); ACC(p1, c.y); ACC(p2, c.z); ACC(p0, c.w);
        ACC(p0, d.x); ACC(p1, d.y); ACC(p2, d.z); ACC(p0, d.w);
    }
    for (; j < n4; j += stride) {
        float4 a = in4[j];
        ACC(p0, a.x); ACC(p1, a.y); ACC(p2, a.z); ACC(p0, a.w);
    }

    // Scalar tail (n_total % 4 != 0) — block 0 only (no-op for this shape)
    if (blockIdx.x == 0) {
        for (int i = n4 * 4 + threadIdx.x; i < n_total; i += BLOCK_THREADS) {
            int c = i % 3;
            atomicAdd(&sh[(c * NBINS + bin_of(in[i])) * 32 + lane], 1u);
        }
    }

    __syncthreads();

    // Reduce the 32 lane-columns per bin (rotated to stay bank-conflict-free),
    // publish block partial to the L2 counters.
    for (int i = threadIdx.x; i < NHIST; i += BLOCK_THREADS) {
        unsigned int s = 0u;
        #pragma unroll
        for (int k = 0; k < 32; k++)
            s += sh[i * 32 + ((k + threadIdx.x) & 31)];
        if (s) atomicAdd(&g_counts[i], s);
    }

    // Fused finalize: last block to arrive normalizes and resets state.
    __threadfence();
    __shared__ unsigned int ticket;
    if (threadIdx.x == 0) ticket = atomicAdd(&g_ticket, 1u);
    __syncthreads();
    if (ticket == GRID_BLOCKS - 1) {
        for (int i = threadIdx.x; i < NHIST; i += BLOCK_THREADS) {
            unsigned int s = atomicAdd(&g_counts[i], 0u);   // coherent read
            g_counts[i] = 0u;                               // reset for next call
            int c   = i >> 8;
            int bin = i & (NBINS - 1);
            // reference output is hist.T -> [nbins, 3] row-major
            out[bin * NCH + c] = (float)s * inv_total;
        }
        if (threadIdx.x == 0) g_ticket = 0u;                // reset ticket
    }
}

extern "C" void kernel_launch(void* const* d_in, const int* in_sizes, int n_in,
                              void* d_out, int out_size) {
    const float* in = (const float*)d_in[0];
    int n = in_sizes[0];                 // 64*512*512*3 = 50,331,648
    int n4 = n / 4;
    float inv_total = 1.0f / (float)(n / 3);   // per-channel pixel count (exact)

    // Raise dynamic-smem limit for the 96 KB table (idempotent, capture-safe).
    cudaFuncSetAttribute(hist_kernel,
                         cudaFuncAttributeMaxDynamicSharedMemorySize, SMEM_BYTES);

    hist_kernel<<<GRID_BLOCKS, BLOCK_THREADS, SMEM_BYTES>>>(
        (const float4*)in, n4, in, n, (float*)d_out, inv_total);
}